// round 5
// baseline (speedup 1.0000x reference)
#include <cuda_runtime.h>

#define N_NODES 100000
#define CIN 128
#define CHID 128
#define COUT 64

// ---------------- scratch ----------------
__device__ __align__(16) float g_sum1[(size_t)N_NODES * CIN];
__device__ __align__(16) float g_deg [N_NODES];
__device__ __align__(16) float g_h   [(size_t)N_NODES * CHID];
__device__ __align__(16) float g_t   [(size_t)N_NODES * COUT];
__device__ __align__(16) float g_r   [(size_t)N_NODES * COUT];
__device__ __align__(16) float g_sum2[(size_t)N_NODES * COUT];
__device__ int g_is64;

// ---------------- packed f32x2 helpers ----------------
__device__ __forceinline__ unsigned long long dupf2(float v) {
    unsigned long long r;
    asm("mov.b64 %0, {%1, %1};" : "=l"(r) : "r"(__float_as_uint(v)));
    return r;
}
__device__ __forceinline__ void fma2(unsigned long long& d,
                                     unsigned long long a, unsigned long long b) {
    asm("fma.rn.f32x2 %0, %1, %2, %0;" : "+l"(d) : "l"(a), "l"(b));
}
__device__ __forceinline__ void unpack2(unsigned long long p, float& lo, float& hi) {
    unsigned int l, h;
    asm("mov.b64 {%0, %1}, %2;" : "=r"(l), "=r"(h) : "l"(p));
    lo = __uint_as_float(l); hi = __uint_as_float(h);
}

// ---------------- zero + flag ----------------
__global__ void zero_kernel() {
    long long i = (long long)blockIdx.x * blockDim.x + threadIdx.x;
    const long long s1 = (long long)(N_NODES * (CIN / 4));
    const long long s2 = (long long)(N_NODES * (COUT / 4));
    float4 z = {0.f, 0.f, 0.f, 0.f};
    if (i < s1) reinterpret_cast<float4*>(g_sum1)[i] = z;
    if (i < s2) reinterpret_cast<float4*>(g_sum2)[i] = z;
    if (i < N_NODES) g_deg[i] = 0.f;
    if (i == 0) g_is64 = 1;
}

// ---------------- detect edge_index dtype ----------------
__global__ void detect_kernel(const long long* __restrict__ ei, long long n) {
    long long i = (long long)blockIdx.x * blockDim.x + threadIdx.x;
    long long stride = (long long)gridDim.x * blockDim.x;
    for (; i < n; i += stride) {
        unsigned long long v = (unsigned long long)ei[i];
        if (v >= (unsigned long long)N_NODES) { g_is64 = 0; return; }
    }
}

// ---------------- edge aggregation, layer 1 ----------------
__global__ void edge_agg1(const float* __restrict__ x,
                          const void* __restrict__ ei_raw, int E) {
    int e    = (blockIdx.x * blockDim.x + threadIdx.x) >> 5;
    int lane = threadIdx.x & 31;
    if (e >= E) return;
    int src, dst;
    if (g_is64) {
        const long long* ei = (const long long*)ei_raw;
        src = (int)ei[e]; dst = (int)ei[(size_t)E + e];
    } else {
        const int* ei = (const int*)ei_raw;
        src = ei[e]; dst = ei[(size_t)E + e];
    }
    if ((unsigned)src >= N_NODES || (unsigned)dst >= N_NODES) return;
    float4 v = *reinterpret_cast<const float4*>(x + (size_t)src * CIN + lane * 4);
    float* d = g_sum1 + (size_t)dst * CIN + lane * 4;
    asm volatile("red.global.add.v4.f32 [%0], {%1, %2, %3, %4};"
                 :: "l"(d), "f"(v.x), "f"(v.y), "f"(v.z), "f"(v.w) : "memory");
    if (lane == 0) atomicAdd(g_deg + dst, 1.0f);
}

// ---------------- edge aggregation, layer 2 ----------------
__global__ void edge_agg2(const void* __restrict__ ei_raw, int E) {
    int idx = blockIdx.x * blockDim.x + threadIdx.x;
    int e   = idx >> 4;
    int l   = idx & 15;
    if (e >= E) return;
    int src, dst;
    if (g_is64) {
        const long long* ei = (const long long*)ei_raw;
        src = (int)ei[e]; dst = (int)ei[(size_t)E + e];
    } else {
        const int* ei = (const int*)ei_raw;
        src = ei[e]; dst = ei[(size_t)E + e];
    }
    if ((unsigned)src >= N_NODES || (unsigned)dst >= N_NODES) return;
    float4 v = *reinterpret_cast<const float4*>(g_t + (size_t)src * COUT + l * 4);
    float* d = g_sum2 + (size_t)dst * COUT + l * 4;
    asm volatile("red.global.add.v4.f32 [%0], {%1, %2, %3, %4};"
                 :: "l"(d), "f"(v.x), "f"(v.y), "f"(v.z), "f"(v.w) : "memory");
}

// ================= GEMM common shape =================
// BM=128, BN=128, BK=32, 256 threads, per-thread 8 rows x 8 cols (32 FFMA2/k).
// tx = tid & 15 -> col group (c0 = tx*8), ty = tid >> 4 -> row group (r0 = ty*8).
// A loader: lm = tid>>1 (node 0..127), lk0 = (tid&1)*16 (16 k each).
#define APITCH 132   // multiple of 4: 16B-aligned rows for LDS.128

// ---------------- GEMM layer 1 ----------------
// h = relu([mean | x] @ [W1l ; W1r] + b1)   A:[N,256]  W:[256,128]
__global__ void __launch_bounds__(256, 1) gemm1(const float* __restrict__ x,
                                                const float* __restrict__ W1l,
                                                const float* __restrict__ W1r,
                                                const float* __restrict__ b1) {
    __shared__ __align__(16) float Ws[32 * 128];
    __shared__ __align__(16) float As[32 * APITCH];

    const int tid = threadIdx.x;
    const int block_m = blockIdx.x * 128;

    const int lm   = tid >> 1;
    const int lk0  = (tid & 1) * 16;
    const int node = block_m + lm;
    const bool valid = (node < N_NODES);
    float rdeg = 1.0f;
    if (valid) rdeg = 1.0f / fmaxf(g_deg[node], 1.0f);

    const int c0 = (tid & 15) * 8;
    const int r0 = (tid >> 4) * 8;

    unsigned long long acc[8][4];   // [col][row-pair]
#pragma unroll
    for (int c = 0; c < 8; c++)
#pragma unroll
        for (int p = 0; p < 4; p++) acc[c][p] = 0ull;

    float4 av[4];   // staging: 16 A elems
    float4 wv[4];   // staging: 16 W elems

    // W loader: 4 float4 per thread. fidx = tid + i*256; kk = fidx>>5; j4 = fidx&31.
    // A: load 16 k for node lm starting at lk0.
    auto load_chunk = [&](int ch) {
        const int kbase = ch * 32;
        // A
        if (valid) {
            if (kbase < 128) {
                const float4* p = reinterpret_cast<const float4*>(
                    g_sum1 + (size_t)node * CIN + kbase + lk0);
#pragma unroll
                for (int i = 0; i < 4; i++) {
                    float4 t = p[i];
                    av[i] = make_float4(t.x * rdeg, t.y * rdeg, t.z * rdeg, t.w * rdeg);
                }
            } else {
                const float4* p = reinterpret_cast<const float4*>(
                    x + (size_t)node * CIN + (kbase - 128) + lk0);
#pragma unroll
                for (int i = 0; i < 4; i++) av[i] = p[i];
            }
        } else {
#pragma unroll
            for (int i = 0; i < 4; i++) av[i] = make_float4(0.f, 0.f, 0.f, 0.f);
        }
        // W
#pragma unroll
        for (int i = 0; i < 4; i++) {
            int fidx = tid + i * 256;
            int kk = fidx >> 5, j4 = fidx & 31;
            int k = kbase + kk;
            const float* wrow = (k < 128) ? (W1l + k * 128) : (W1r + (k - 128) * 128);
            wv[i] = *reinterpret_cast<const float4*>(wrow + j4 * 4);
        }
    };
    auto store_chunk = [&]() {
#pragma unroll
        for (int i = 0; i < 4; i++) {
            float t[4] = {av[i].x, av[i].y, av[i].z, av[i].w};
#pragma unroll
            for (int j = 0; j < 4; j++)
                As[(lk0 + i * 4 + j) * APITCH + lm] = t[j];
        }
#pragma unroll
        for (int i = 0; i < 4; i++) {
            int fidx = tid + i * 256;
            int kk = fidx >> 5, j4 = fidx & 31;
            *reinterpret_cast<float4*>(&Ws[kk * 128 + j4 * 4]) = wv[i];
        }
    };

    load_chunk(0);
    for (int ch = 0; ch < 8; ch++) {
        store_chunk();
        __syncthreads();
        if (ch + 1 < 8) load_chunk(ch + 1);   // LDGs in flight during compute

#pragma unroll 8
        for (int kk = 0; kk < 32; kk++) {
            float4 w0 = *reinterpret_cast<const float4*>(&Ws[kk * 128 + c0]);
            float4 w1 = *reinterpret_cast<const float4*>(&Ws[kk * 128 + c0 + 4]);
            const unsigned long long* ap =
                reinterpret_cast<const unsigned long long*>(&As[kk * APITCH + r0]);
            unsigned long long a0 = ap[0], a1 = ap[1], a2 = ap[2], a3 = ap[3];
            unsigned long long wd[8];
            wd[0] = dupf2(w0.x); wd[1] = dupf2(w0.y);
            wd[2] = dupf2(w0.z); wd[3] = dupf2(w0.w);
            wd[4] = dupf2(w1.x); wd[5] = dupf2(w1.y);
            wd[6] = dupf2(w1.z); wd[7] = dupf2(w1.w);
#pragma unroll
            for (int c = 0; c < 8; c++) {
                fma2(acc[c][0], wd[c], a0);
                fma2(acc[c][1], wd[c], a1);
                fma2(acc[c][2], wd[c], a2);
                fma2(acc[c][3], wd[c], a3);
            }
        }
        __syncthreads();
    }

    float bv[8];
#pragma unroll
    for (int c = 0; c < 8; c++) bv[c] = b1[c0 + c];
#pragma unroll
    for (int p = 0; p < 4; p++) {
        float lo[8], hi[8];
#pragma unroll
        for (int c = 0; c < 8; c++) unpack2(acc[c][p], lo[c], hi[c]);
        int n0 = block_m + r0 + 2 * p;
        if (n0 < N_NODES) {
            float4 o0 = {fmaxf(lo[0] + bv[0], 0.f), fmaxf(lo[1] + bv[1], 0.f),
                         fmaxf(lo[2] + bv[2], 0.f), fmaxf(lo[3] + bv[3], 0.f)};
            float4 o1 = {fmaxf(lo[4] + bv[4], 0.f), fmaxf(lo[5] + bv[5], 0.f),
                         fmaxf(lo[6] + bv[6], 0.f), fmaxf(lo[7] + bv[7], 0.f)};
            *reinterpret_cast<float4*>(g_h + (size_t)n0 * CHID + c0) = o0;
            *reinterpret_cast<float4*>(g_h + (size_t)n0 * CHID + c0 + 4) = o1;
        }
        if (n0 + 1 < N_NODES) {
            float4 o0 = {fmaxf(hi[0] + bv[0], 0.f), fmaxf(hi[1] + bv[1], 0.f),
                         fmaxf(hi[2] + bv[2], 0.f), fmaxf(hi[3] + bv[3], 0.f)};
            float4 o1 = {fmaxf(hi[4] + bv[4], 0.f), fmaxf(hi[5] + bv[5], 0.f),
                         fmaxf(hi[6] + bv[6], 0.f), fmaxf(hi[7] + bv[7], 0.f)};
            *reinterpret_cast<float4*>(g_h + (size_t)(n0 + 1) * CHID + c0) = o0;
            *reinterpret_cast<float4*>(g_h + (size_t)(n0 + 1) * CHID + c0 + 4) = o1;
        }
    }
}

// ---------------- GEMM layer 2 ----------------
// [t | r] = h @ [W2l | W2r] (+ [0 | b2])   A:[N,128]  W:[128,128]
__global__ void __launch_bounds__(256, 1) gemm2(const float* __restrict__ W2l,
                                                const float* __restrict__ W2r,
                                                const float* __restrict__ b2) {
    __shared__ __align__(16) float Ws[32 * 128];
    __shared__ __align__(16) float As[32 * APITCH];

    const int tid = threadIdx.x;
    const int block_m = blockIdx.x * 128;

    const int lm   = tid >> 1;
    const int lk0  = (tid & 1) * 16;
    const int node = block_m + lm;
    const bool valid = (node < N_NODES);

    const int c0 = (tid & 15) * 8;
    const int r0 = (tid >> 4) * 8;

    unsigned long long acc[8][4];
#pragma unroll
    for (int c = 0; c < 8; c++)
#pragma unroll
        for (int p = 0; p < 4; p++) acc[c][p] = 0ull;

    float4 av[4];
    float4 wv[4];

    auto load_chunk = [&](int ch) {
        const int kbase = ch * 32;
        if (valid) {
            const float4* p = reinterpret_cast<const float4*>(
                g_h + (size_t)node * CHID + kbase + lk0);
#pragma unroll
            for (int i = 0; i < 4; i++) av[i] = p[i];
        } else {
#pragma unroll
            for (int i = 0; i < 4; i++) av[i] = make_float4(0.f, 0.f, 0.f, 0.f);
        }
#pragma unroll
        for (int i = 0; i < 4; i++) {
            int fidx = tid + i * 256;
            int kk = fidx >> 5, j4 = fidx & 31;
            int k = kbase + kk;
            const float* wrow = (j4 < 16) ? (W2l + k * 64 + j4 * 4)
                                          : (W2r + k * 64 + (j4 - 16) * 4);
            wv[i] = *reinterpret_cast<const float4*>(wrow);
        }
    };
    auto store_chunk = [&]() {
#pragma unroll
        for (int i = 0; i < 4; i++) {
            float t[4] = {av[i].x, av[i].y, av[i].z, av[i].w};
#pragma unroll
            for (int j = 0; j < 4; j++)
                As[(lk0 + i * 4 + j) * APITCH + lm] = t[j];
        }
#pragma unroll
        for (int i = 0; i < 4; i++) {
            int fidx = tid + i * 256;
            int kk = fidx >> 5, j4 = fidx & 31;
            *reinterpret_cast<float4*>(&Ws[kk * 128 + j4 * 4]) = wv[i];
        }
    };

    load_chunk(0);
    for (int ch = 0; ch < 4; ch++) {
        store_chunk();
        __syncthreads();
        if (ch + 1 < 4) load_chunk(ch + 1);

#pragma unroll 8
        for (int kk = 0; kk < 32; kk++) {
            float4 w0 = *reinterpret_cast<const float4*>(&Ws[kk * 128 + c0]);
            float4 w1 = *reinterpret_cast<const float4*>(&Ws[kk * 128 + c0 + 4]);
            const unsigned long long* ap =
                reinterpret_cast<const unsigned long long*>(&As[kk * APITCH + r0]);
            unsigned long long a0 = ap[0], a1 = ap[1], a2 = ap[2], a3 = ap[3];
            unsigned long long wd[8];
            wd[0] = dupf2(w0.x); wd[1] = dupf2(w0.y);
            wd[2] = dupf2(w0.z); wd[3] = dupf2(w0.w);
            wd[4] = dupf2(w1.x); wd[5] = dupf2(w1.y);
            wd[6] = dupf2(w1.z); wd[7] = dupf2(w1.w);
#pragma unroll
            for (int c = 0; c < 8; c++) {
                fma2(acc[c][0], wd[c], a0);
                fma2(acc[c][1], wd[c], a1);
                fma2(acc[c][2], wd[c], a2);
                fma2(acc[c][3], wd[c], a3);
            }
        }
        __syncthreads();
    }

    // cols [0,64): t (tx 0..7); cols [64,128): r = . + b2 (tx 8..15)
    const bool is_t = (c0 < 64);
    const int cc = is_t ? c0 : (c0 - 64);
    float bv[8];
#pragma unroll
    for (int c = 0; c < 8; c++) bv[c] = is_t ? 0.f : b2[cc + c];
    float* dstbase = is_t ? g_t : g_r;

#pragma unroll
    for (int p = 0; p < 4; p++) {
        float lo[8], hi[8];
#pragma unroll
        for (int c = 0; c < 8; c++) unpack2(acc[c][p], lo[c], hi[c]);
        int n0 = block_m + r0 + 2 * p;
        if (n0 < N_NODES) {
            float4 o0 = {lo[0] + bv[0], lo[1] + bv[1], lo[2] + bv[2], lo[3] + bv[3]};
            float4 o1 = {lo[4] + bv[4], lo[5] + bv[5], lo[6] + bv[6], lo[7] + bv[7]};
            *reinterpret_cast<float4*>(dstbase + (size_t)n0 * COUT + cc) = o0;
            *reinterpret_cast<float4*>(dstbase + (size_t)n0 * COUT + cc + 4) = o1;
        }
        if (n0 + 1 < N_NODES) {
            float4 o0 = {hi[0] + bv[0], hi[1] + bv[1], hi[2] + bv[2], hi[3] + bv[3]};
            float4 o1 = {hi[4] + bv[4], hi[5] + bv[5], hi[6] + bv[6], hi[7] + bv[7]};
            *reinterpret_cast<float4*>(dstbase + (size_t)(n0 + 1) * COUT + cc) = o0;
            *reinterpret_cast<float4*>(dstbase + (size_t)(n0 + 1) * COUT + cc + 4) = o1;
        }
    }
}

// ---------------- final: out = sum2/clip(deg,1) + r ----------------
__global__ void final_kernel(float* __restrict__ out) {
    int i = blockIdx.x * blockDim.x + threadIdx.x;
    if (i >= N_NODES * (COUT / 4)) return;
    int n = i >> 4;
    float rd = 1.0f / fmaxf(g_deg[n], 1.0f);
    float4 s = reinterpret_cast<const float4*>(g_sum2)[i];
    float4 r = reinterpret_cast<const float4*>(g_r)[i];
    float4 o = {s.x * rd + r.x, s.y * rd + r.y, s.z * rd + r.z, s.w * rd + r.w};
    reinterpret_cast<float4*>(out)[i] = o;
}

// ---------------- launch ----------------
extern "C" void kernel_launch(void* const* d_in, const int* in_sizes, int n_in,
                              void* d_out, int out_size) {
    const float* x   = (const float*)d_in[0];
    const void*  ei  = d_in[1];
    const float* W1l = (const float*)d_in[2];
    const float* W1r = (const float*)d_in[3];
    const float* b1  = (const float*)d_in[4];
    const float* W2l = (const float*)d_in[5];
    const float* W2r = (const float*)d_in[6];
    const float* b2  = (const float*)d_in[7];
    float* out = (float*)d_out;

    const int E = in_sizes[1] / 2;

    {
        long long tot = (long long)N_NODES * (CIN / 4);
        int blocks = (int)((tot + 255) / 256);
        zero_kernel<<<blocks, 256>>>();
    }
    {
        long long n64_safe = (long long)E / 2;
        detect_kernel<<<1024, 256>>>((const long long*)ei, n64_safe);
    }
    {
        long long threads = (long long)E * 32;
        int blocks = (int)((threads + 255) / 256);
        edge_agg1<<<blocks, 256>>>(x, ei, E);
    }
    {
        int blocks = (N_NODES + 127) / 128;
        gemm1<<<blocks, 256>>>(x, W1l, W1r, b1);
        gemm2<<<blocks, 256>>>(W2l, W2r, b2);
    }
    {
        long long threads = (long long)E * 16;
        int blocks = (int)((threads + 255) / 256);
        edge_agg2<<<blocks, 256>>>(ei, E);
    }
    {
        int blocks = (N_NODES * (COUT / 4) + 255) / 256;
        final_kernel<<<blocks, 256>>>(out);
    }
}